// round 1
// baseline (speedup 1.0000x reference)
#include <cuda_runtime.h>

#define KN 26
#define D  32
#define WPB 8
#define TPB (WPB * 32)
#define WSTRIDE 66   // padded row stride (words) for transposed weights: conflict-free LDS.64

__device__ __forceinline__ float tanh_fast(float x) {
    float y;
    asm("tanh.approx.f32 %0, %1;" : "=f"(y) : "f"(x));
    return y;
}

// 64-wide matvec: xs[0..63] staged per-warp in smem, wrow = transposed weight row for this lane.
__device__ __forceinline__ float matvec64(const float* __restrict__ xs,
                                          const float* __restrict__ wrow,
                                          float acc) {
#pragma unroll
    for (int i = 0; i < 64; i += 2) {
        float2 xv = *reinterpret_cast<const float2*>(xs + i);    // broadcast (free)
        float2 wv = *reinterpret_cast<const float2*>(wrow + i);  // conflict-free per 16-lane phase
        acc = fmaf(xv.x, wv.x, acc);
        acc = fmaf(xv.y, wv.y, acc);
    }
    return acc;
}

__global__ __launch_bounds__(TPB) void moe_kernel(
    int n,
    const float* __restrict__ states,
    const int*   __restrict__ nbr,
    const int*   __restrict__ tiers,
    const float* __restrict__ W_loc,  const float* __restrict__ b_loc,
    const float* __restrict__ W_msg,  const float* __restrict__ b_msg,
    const float* __restrict__ W_fun,  const float* __restrict__ b_fun,
    const float* __restrict__ W_cnf,  const float* __restrict__ b_cnf,
    const float* __restrict__ W_gate, const float* __restrict__ b_gate,
    float* __restrict__ out)
{
    __shared__ float sWloc[D * WSTRIDE];
    __shared__ float sWfun[D * WSTRIDE];
    __shared__ float sWcnf[D * WSTRIDE];
    __shared__ float sWg[128 * 3];
    __shared__ float sXs[WPB * 64];

    // Stage weights transposed: sW[j*WSTRIDE + i] = W[i*32 + j]  (i in 0..63)
    for (int e = threadIdx.x; e < 64 * D; e += TPB) {
        int i = e >> 5, j = e & 31;
        sWloc[j * WSTRIDE + i] = W_loc[e];
        sWfun[j * WSTRIDE + i] = W_fun[e];
        sWcnf[j * WSTRIDE + i] = W_cnf[e];
    }
    for (int e = threadIdx.x; e < 128 * 3; e += TPB) sWg[e] = W_gate[e];
    __syncthreads();

    const int lane = threadIdx.x & 31;
    const int warp = threadIdx.x >> 5;
    const int cell = blockIdx.x * WPB + warp;
    if (cell >= n) return;

    float* xs = sXs + warp * 64;
    const unsigned FULL = 0xffffffffu;

    const float cur = states[cell * D + lane];

    // W_msg column cached in registers (lane j holds W_msg[:, j])
    float wm[D];
#pragma unroll
    for (int i = 0; i < D; i++) wm[i] = __ldg(W_msg + i * D + lane);
    const float bmsg = __ldg(b_msg + lane);

    int my_idx = 0, my_tier = -1;
    if (lane < KN) {
        my_idx  = nbr  [cell * KN + lane];
        my_tier = tiers[cell * KN + lane];
    }

    float a0 = 0.f, a1 = 0.f, a2 = 0.f, fmsg = 0.f;
    int c0 = 0, c1 = 0, c2 = 0;

#pragma unroll 2
    for (int k = 0; k < KN; k++) {
        int   idx = __shfl_sync(FULL, my_idx,  k);   // warp-uniform
        int   t   = __shfl_sync(FULL, my_tier, k);   // warp-uniform -> no divergence
        float v   = __ldg(states + idx * D + lane);  // coalesced 128B gather (L2 resident)
        if (t == 1) {
            a1 += v; c1++;
            // per-neighbor message matvec (only needed for tier-1 neighbors!)
            __syncwarp();
            xs[lane] = v;
            __syncwarp();
            float m = bmsg;
#pragma unroll
            for (int i = 0; i < D; i += 2) {
                float2 vv = *reinterpret_cast<const float2*>(xs + i);  // broadcast
                m = fmaf(vv.x, wm[i],     m);
                m = fmaf(vv.y, wm[i + 1], m);
            }
            fmsg += tanh_fast(m);
        } else if (t == 0) { a0 += v; c0++; }
        else               { a2 += v; c2++; }
    }

    const float inv0 = 1.f / (float)max(c0, 1);
    const float inv1 = 1.f / (float)max(c1, 1);
    const float inv2 = 1.f / (float)max(c2, 1);
    a0 *= inv0; a1 *= inv1; a2 *= inv2; fmsg *= inv1;

    // local expert: tanh([cur ; local_agg] @ W_loc + b_loc)
    __syncwarp();
    xs[lane] = cur; xs[D + lane] = a0;
    __syncwarp();
    const float loc = tanh_fast(matvec64(xs, sWloc + lane * WSTRIDE, __ldg(b_loc + lane)));

    // functional expert: tanh([cur ; func_msg] @ W_fun + b_fun)
    __syncwarp();
    xs[D + lane] = fmsg;
    __syncwarp();
    const float fun = tanh_fast(matvec64(xs, sWfun + lane * WSTRIDE, __ldg(b_fun + lane)));

    // distant expert: 3-step explicit Euler CNF conditioned on dist_agg
    const float bcnf = __ldg(b_cnf + lane);
    __syncwarp();
    xs[D + lane] = a2;
    float x = cur;
#pragma unroll
    for (int s = 0; s < 3; s++) {
        __syncwarp();
        xs[lane] = x;
        __syncwarp();
        x = fmaf(1.0f / 3.0f, tanh_fast(matvec64(xs, sWcnf + lane * WSTRIDE, bcnf)), x);
    }

    // gate: softmax([cur;a0;a1;a2] @ W_gate + b_gate); lane-parallel partials + butterfly reduce
    float p0 = fmaf(cur, sWg[lane * 3 + 0], 0.f);
    float p1 = fmaf(cur, sWg[lane * 3 + 1], 0.f);
    float p2 = fmaf(cur, sWg[lane * 3 + 2], 0.f);
    p0 = fmaf(a0, sWg[(D + lane) * 3 + 0], p0);
    p1 = fmaf(a0, sWg[(D + lane) * 3 + 1], p1);
    p2 = fmaf(a0, sWg[(D + lane) * 3 + 2], p2);
    p0 = fmaf(a1, sWg[(2 * D + lane) * 3 + 0], p0);
    p1 = fmaf(a1, sWg[(2 * D + lane) * 3 + 1], p1);
    p2 = fmaf(a1, sWg[(2 * D + lane) * 3 + 2], p2);
    p0 = fmaf(a2, sWg[(3 * D + lane) * 3 + 0], p0);
    p1 = fmaf(a2, sWg[(3 * D + lane) * 3 + 1], p1);
    p2 = fmaf(a2, sWg[(3 * D + lane) * 3 + 2], p2);
#pragma unroll
    for (int o = 16; o > 0; o >>= 1) {
        p0 += __shfl_xor_sync(FULL, p0, o);
        p1 += __shfl_xor_sync(FULL, p1, o);
        p2 += __shfl_xor_sync(FULL, p2, o);
    }
    const float g0 = p0 + __ldg(b_gate + 0);
    const float g1 = p1 + __ldg(b_gate + 1);
    const float g2 = p2 + __ldg(b_gate + 2);
    const float mx = fmaxf(g0, fmaxf(g1, g2));
    const float e0 = __expf(g0 - mx), e1 = __expf(g1 - mx), e2 = __expf(g2 - mx);
    const float inv = 1.f / (e0 + e1 + e2);

    out[cell * D + lane] = (e0 * loc + e1 * fun + e2 * x) * inv;
}

extern "C" void kernel_launch(void* const* d_in, const int* in_sizes, int n_in,
                              void* d_out, int out_size) {
    const float* states = (const float*)d_in[0];
    const int*   nbr    = (const int*)  d_in[1];
    const int*   tiers  = (const int*)  d_in[2];
    const float* W_loc  = (const float*)d_in[3];
    const float* b_loc  = (const float*)d_in[4];
    const float* W_msg  = (const float*)d_in[5];
    const float* b_msg  = (const float*)d_in[6];
    const float* W_fun  = (const float*)d_in[7];
    const float* b_fun  = (const float*)d_in[8];
    const float* W_cnf  = (const float*)d_in[9];
    const float* b_cnf  = (const float*)d_in[10];
    const float* W_gate = (const float*)d_in[11];
    const float* b_gate = (const float*)d_in[12];
    float* out = (float*)d_out;

    const int n = in_sizes[0] / D;
    const int blocks = (n + WPB - 1) / WPB;
    moe_kernel<<<blocks, TPB>>>(n, states, nbr, tiers,
                                W_loc, b_loc, W_msg, b_msg,
                                W_fun, b_fun, W_cnf, b_cnf,
                                W_gate, b_gate, out);
}

// round 2
// speedup vs baseline: 1.5176x; 1.5176x over previous
#include <cuda_runtime.h>

#define D    32
#define KN   26
#define CPW  4              // cells per warp
#define WPB  8              // warps per block
#define TPB  (WPB * 32)
#define NMAX 125000
#define WSTR 33             // weight smem row stride (conflict-free LDS/STS)
#define XSTR 36             // x staging row stride (16B-aligned float4 reads)

__device__ float g_msg[NMAX * D];   // precomputed tanh(state @ W_msg + b_msg)

__device__ __forceinline__ float tanh_fast(float x) {
    float y;
    asm("tanh.approx.f32 %0, %1;" : "=f"(y) : "f"(x));
    return y;
}

// ---------------------------------------------------------------------------
// Prepass: g_msg[cell] = tanh(states[cell] @ W_msg + b_msg)   (per SOURCE cell)
// ---------------------------------------------------------------------------
__global__ __launch_bounds__(TPB) void msg_prepass(
    int n, const float* __restrict__ states,
    const float* __restrict__ W_msg, const float* __restrict__ b_msg)
{
    __shared__ float sx[WPB][CPW * XSTR];
    const int lane = threadIdx.x & 31, warp = threadIdx.x >> 5;
    const int base = (blockIdx.x * WPB + warp) * CPW;
    if (base >= n) return;

    float wm[D];                                   // lane holds W_msg[:, lane]
#pragma unroll
    for (int i = 0; i < D; i++) wm[i] = __ldg(W_msg + i * D + lane);
    const float bm = __ldg(b_msg + lane);

    float* xb = sx[warp];
#pragma unroll
    for (int c = 0; c < CPW; c++) {
        int cell = base + c;
        xb[c * XSTR + lane] = (cell < n) ? states[cell * D + lane] : 0.f;
    }
    __syncwarp();
#pragma unroll
    for (int c = 0; c < CPW; c++) {
        int cell = base + c;
        float m = bm;
#pragma unroll
        for (int i8 = 0; i8 < 8; i8++) {
            float4 xv = *reinterpret_cast<const float4*>(xb + c * XSTR + 4 * i8);
            m = fmaf(xv.x, wm[4 * i8 + 0], m);
            m = fmaf(xv.y, wm[4 * i8 + 1], m);
            m = fmaf(xv.z, wm[4 * i8 + 2], m);
            m = fmaf(xv.w, wm[4 * i8 + 3], m);
        }
        if (cell < n) g_msg[cell * D + lane] = tanh_fast(m);
    }
}

// ---------------------------------------------------------------------------
// Main kernel: 4 cells per warp, fused expert matvecs, register gate
// ---------------------------------------------------------------------------
__global__ __launch_bounds__(TPB) void moe_main(
    int n,
    const float* __restrict__ states,
    const int*   __restrict__ nbr,
    const int*   __restrict__ tiers,
    const float* __restrict__ W_loc,  const float* __restrict__ b_loc,
    const float* __restrict__ W_fun,  const float* __restrict__ b_fun,
    const float* __restrict__ W_cnf,  const float* __restrict__ b_cnf,
    const float* __restrict__ W_gate, const float* __restrict__ b_gate,
    float* __restrict__ out)
{
    __shared__ float  sWloc[64 * WSTR];            // sW[i*WSTR + j] = W[i*32 + j]
    __shared__ float  sWfun[64 * WSTR];
    __shared__ float  sWcnf[64 * WSTR];
    __shared__ float4 sIn[WPB][CPW * D];           // {cur, a0, fmsg, a2} per (cell, i)
    __shared__ float  sX[WPB][CPW * XSTR];         // CNF x staging

    // stage weights (coalesced LDG, stride-1 STS: conflict-free)
    for (int e = threadIdx.x; e < 64 * D; e += TPB) {
        int i = e >> 5, j = e & 31;
        sWloc[i * WSTR + j] = W_loc[e];
        sWfun[i * WSTR + j] = W_fun[e];
        sWcnf[i * WSTR + j] = W_cnf[e];
    }
    __syncthreads();

    const int lane = threadIdx.x & 31, warp = threadIdx.x >> 5;
    const int base = (blockIdx.x * WPB + warp) * CPW;
    if (base >= n) return;
    const unsigned FULL = 0xffffffffu;

    // per-thread cached small params
    const float bl = __ldg(b_loc + lane);
    const float bf = __ldg(b_fun + lane);
    const float bc = __ldg(b_cnf + lane);
    const float bg0 = __ldg(b_gate + 0), bg1 = __ldg(b_gate + 1), bg2 = __ldg(b_gate + 2);
    float wg[4][3];
#pragma unroll
    for (int s = 0; s < 4; s++)
#pragma unroll
        for (int e = 0; e < 3; e++)
            wg[s][e] = __ldg(W_gate + (s * D + lane) * 3 + e);

    float cur[CPW], A0[CPW], A1[CPW], A2[CPW];
    float4* inb = sIn[warp];
    float*  xxb = sX[warp];

    // ---- gather + tier means + message gather (one cell at a time) ----
#pragma unroll
    for (int c = 0; c < CPW; c++) {
        const int cell = base + c;
        const bool act = (cell < n);

        float cu = act ? states[cell * D + lane] : 0.f;
        int mypk = 3;                               // tier 3 = ignore
        if (act && lane < KN) {
            int idx = __ldg(nbr   + cell * KN + lane);
            int tr  = __ldg(tiers + cell * KN + lane);
            mypk = (idx << 2) | tr;
        }
        float a0 = 0.f, a1 = 0.f, a2 = 0.f, fm = 0.f;
        float n0 = 0.f, n1 = 0.f, n2 = 0.f;
#pragma unroll
        for (int k = 0; k < KN; k++) {
            int pk = __shfl_sync(FULL, mypk, k);    // warp-uniform
            int j  = pk >> 2;
            int t  = pk & 3;
            if (t < 3) {
                float v = __ldg(states + j * D + lane);
                if (t == 1) {
                    a1 += v; n1 += 1.f;
                    fm += __ldg(g_msg + j * D + lane);
                } else if (t == 0) { a0 += v; n0 += 1.f; }
                else               { a2 += v; n2 += 1.f; }
            }
        }
        a0 = __fdividef(a0, fmaxf(n0, 1.f));
        a1 = __fdividef(a1, fmaxf(n1, 1.f));
        a2 = __fdividef(a2, fmaxf(n2, 1.f));
        fm = __fdividef(fm, fmaxf(n1, 1.f));

        cur[c] = cu; A0[c] = a0; A1[c] = a1; A2[c] = a2;
        inb[c * D + lane] = make_float4(cu, a0, fm, a2);   // STS.128
    }
    __syncwarp();

    // ---- fused pass: loc, fun, and CNF conditioning half (h2), 4 cells ----
    float accL[CPW], accF[CPW], h2[CPW];
#pragma unroll
    for (int c = 0; c < CPW; c++) { accL[c] = bl; accF[c] = bf; h2[c] = bc; }

#pragma unroll
    for (int i = 0; i < D; i++) {
        const float wlT = sWloc[i * WSTR + lane];
        const float wlB = sWloc[(D + i) * WSTR + lane];
        const float wfT = sWfun[i * WSTR + lane];
        const float wfB = sWfun[(D + i) * WSTR + lane];
        const float wcB = sWcnf[(D + i) * WSTR + lane];
#pragma unroll
        for (int c = 0; c < CPW; c++) {
            const float4 xi = inb[c * D + i];       // broadcast LDS.128
            accL[c] = fmaf(xi.x, wlT, fmaf(xi.y, wlB, accL[c]));
            accF[c] = fmaf(xi.x, wfT, fmaf(xi.z, wfB, accF[c]));
            h2[c]   = fmaf(xi.w, wcB, h2[c]);
        }
    }
    float loc[CPW], fun[CPW], x[CPW];
#pragma unroll
    for (int c = 0; c < CPW; c++) {
        loc[c] = tanh_fast(accL[c]);
        fun[c] = tanh_fast(accF[c]);
        x[c]   = cur[c];
    }

    // ---- CNF: 3 explicit-Euler steps, top half only (h2 reused) ----
#pragma unroll
    for (int s = 0; s < 3; s++) {
        __syncwarp();
#pragma unroll
        for (int c = 0; c < CPW; c++) xxb[c * XSTR + lane] = x[c];
        __syncwarp();
        float acc[CPW];
#pragma unroll
        for (int c = 0; c < CPW; c++) acc[c] = h2[c];
#pragma unroll
        for (int i8 = 0; i8 < 8; i8++) {
            const float w0 = sWcnf[(4 * i8 + 0) * WSTR + lane];
            const float w1 = sWcnf[(4 * i8 + 1) * WSTR + lane];
            const float w2 = sWcnf[(4 * i8 + 2) * WSTR + lane];
            const float w3 = sWcnf[(4 * i8 + 3) * WSTR + lane];
#pragma unroll
            for (int c = 0; c < CPW; c++) {
                const float4 xv = *reinterpret_cast<const float4*>(xxb + c * XSTR + 4 * i8);
                acc[c] = fmaf(xv.x, w0, fmaf(xv.y, w1, fmaf(xv.z, w2, fmaf(xv.w, w3, acc[c]))));
            }
        }
#pragma unroll
        for (int c = 0; c < CPW; c++)
            x[c] = fmaf(1.0f / 3.0f, tanh_fast(acc[c]), x[c]);
    }

    // ---- gate (register weights + butterfly) + combine + store ----
#pragma unroll
    for (int c = 0; c < CPW; c++) {
        float p0 = cur[c] * wg[0][0] + A0[c] * wg[1][0] + A1[c] * wg[2][0] + A2[c] * wg[3][0];
        float p1 = cur[c] * wg[0][1] + A0[c] * wg[1][1] + A1[c] * wg[2][1] + A2[c] * wg[3][1];
        float p2 = cur[c] * wg[0][2] + A0[c] * wg[1][2] + A1[c] * wg[2][2] + A2[c] * wg[3][2];
#pragma unroll
        for (int o = 16; o > 0; o >>= 1) {
            p0 += __shfl_xor_sync(FULL, p0, o);
            p1 += __shfl_xor_sync(FULL, p1, o);
            p2 += __shfl_xor_sync(FULL, p2, o);
        }
        const float g0 = p0 + bg0, g1 = p1 + bg1, g2 = p2 + bg2;
        const float mx = fmaxf(g0, fmaxf(g1, g2));
        const float e0 = __expf(g0 - mx), e1 = __expf(g1 - mx), e2 = __expf(g2 - mx);
        const float inv = __fdividef(1.f, e0 + e1 + e2);

        const int cell = base + c;
        if (cell < n)
            out[cell * D + lane] = (e0 * loc[c] + e1 * fun[c] + e2 * x[c]) * inv;
    }
}

extern "C" void kernel_launch(void* const* d_in, const int* in_sizes, int n_in,
                              void* d_out, int out_size) {
    const float* states = (const float*)d_in[0];
    const int*   nbr    = (const int*)  d_in[1];
    const int*   tiers  = (const int*)  d_in[2];
    const float* W_loc  = (const float*)d_in[3];
    const float* b_loc  = (const float*)d_in[4];
    const float* W_msg  = (const float*)d_in[5];
    const float* b_msg  = (const float*)d_in[6];
    const float* W_fun  = (const float*)d_in[7];
    const float* b_fun  = (const float*)d_in[8];
    const float* W_cnf  = (const float*)d_in[9];
    const float* b_cnf  = (const float*)d_in[10];
    const float* W_gate = (const float*)d_in[11];
    const float* b_gate = (const float*)d_in[12];
    float* out = (float*)d_out;

    const int n = in_sizes[0] / D;
    const int blocks = (n + WPB * CPW - 1) / (WPB * CPW);

    msg_prepass<<<blocks, TPB>>>(n, states, W_msg, b_msg);
    moe_main<<<blocks, TPB>>>(n, states, nbr, tiers,
                              W_loc, b_loc, W_fun, b_fun,
                              W_cnf, b_cnf, W_gate, b_gate, out);
}

// round 3
// speedup vs baseline: 2.0042x; 1.3206x over previous
#include <cuda_runtime.h>

#define D    32
#define KN   26
#define CPW  4              // cells per warp
#define WPB  8              // warps per block
#define TPB  (WPB * 32)
#define NMAX 125000
#define WSTR 32             // weight smem row stride (i*WSTR+lane is stride-1 across lanes)
#define XSTR 36             // x staging row stride (16B-aligned float4 reads)

__device__ float g_msg[NMAX * D];   // precomputed tanh(state @ W_msg + b_msg)

__device__ __forceinline__ float tanh_fast(float x) {
    float y;
    asm("tanh.approx.f32 %0, %1;" : "=f"(y) : "f"(x));
    return y;
}

// ---------------------------------------------------------------------------
// Prepass: g_msg[cell] = tanh(states[cell] @ W_msg + b_msg)   (per SOURCE cell)
// ---------------------------------------------------------------------------
__global__ __launch_bounds__(TPB) void msg_prepass(
    int n, const float* __restrict__ states,
    const float* __restrict__ W_msg, const float* __restrict__ b_msg)
{
    __shared__ float sx[WPB][CPW * XSTR];
    const int lane = threadIdx.x & 31, warp = threadIdx.x >> 5;
    const int base = (blockIdx.x * WPB + warp) * CPW;
    if (base >= n) return;

    float wm[D];                                   // lane holds W_msg[:, lane]
#pragma unroll
    for (int i = 0; i < D; i++) wm[i] = __ldg(W_msg + i * D + lane);
    const float bm = __ldg(b_msg + lane);

    float* xb = sx[warp];
#pragma unroll
    for (int c = 0; c < CPW; c++) {
        int cell = base + c;
        xb[c * XSTR + lane] = (cell < n) ? states[cell * D + lane] : 0.f;
    }
    __syncwarp();
#pragma unroll
    for (int c = 0; c < CPW; c++) {
        int cell = base + c;
        float m = bm;
#pragma unroll
        for (int i8 = 0; i8 < 8; i8++) {
            float4 xv = *reinterpret_cast<const float4*>(xb + c * XSTR + 4 * i8);
            m = fmaf(xv.x, wm[4 * i8 + 0], m);
            m = fmaf(xv.y, wm[4 * i8 + 1], m);
            m = fmaf(xv.z, wm[4 * i8 + 2], m);
            m = fmaf(xv.w, wm[4 * i8 + 3], m);
        }
        if (cell < n) g_msg[cell * D + lane] = tanh_fast(m);
    }
}

// ---------------------------------------------------------------------------
// Main kernel: 4 cells/warp, fused expert matvecs, minimal register liveness
// ---------------------------------------------------------------------------
__global__ __launch_bounds__(TPB, 5) void moe_main(
    int n,
    const float* __restrict__ states,
    const int*   __restrict__ nbr,
    const int*   __restrict__ tiers,
    const float* __restrict__ W_loc,  const float* __restrict__ b_loc,
    const float* __restrict__ W_fun,  const float* __restrict__ b_fun,
    const float* __restrict__ W_cnf,  const float* __restrict__ b_cnf,
    const float* __restrict__ W_gate, const float* __restrict__ b_gate,
    float* __restrict__ out)
{
    __shared__ float  sWloc[64 * WSTR];            // sW[i*WSTR + j] = W[i*32 + j]
    __shared__ float  sWfun[64 * WSTR];
    __shared__ float  sWcnf[64 * WSTR];
    __shared__ float4 sIn[WPB][CPW * D];           // {cur, a0, fmsg, a2} per (cell, i)
    __shared__ float  sX[WPB][CPW * XSTR];         // CNF x staging

    // stage weights (coalesced LDG, stride-1 STS: conflict-free)
    for (int e = threadIdx.x; e < 64 * D; e += TPB) {
        int i = e >> 5, j = e & 31;
        sWloc[i * WSTR + j] = W_loc[e];
        sWfun[i * WSTR + j] = W_fun[e];
        sWcnf[i * WSTR + j] = W_cnf[e];
    }
    __syncthreads();

    const int lane = threadIdx.x & 31, warp = threadIdx.x >> 5;
    const int base = (blockIdx.x * WPB + warp) * CPW;
    if (base >= n) return;
    const unsigned FULL = 0xffffffffu;

    float4* inb = sIn[warp];
    float*  xxb = sX[warp];

    float A1[CPW];                                 // func_agg kept in regs (only agg not in sIn)

    // ---- gather + tier means + message gather (one cell at a time) ----
#pragma unroll
    for (int c = 0; c < CPW; c++) {
        const int cell = base + c;
        const bool act = (cell < n);

        float cu = act ? states[cell * D + lane] : 0.f;
        int mypk = 3;                               // tier 3 = ignore
        if (act && lane < KN) {
            int idx = __ldg(nbr   + cell * KN + lane);
            int tr  = __ldg(tiers + cell * KN + lane);
            mypk = (idx << 2) | tr;
        }
        float a0 = 0.f, a1 = 0.f, a2 = 0.f, fm = 0.f;
        float n0 = 0.f, n1 = 0.f, n2 = 0.f;
#pragma unroll
        for (int k = 0; k < KN; k++) {
            int pk = __shfl_sync(FULL, mypk, k);    // warp-uniform
            int j  = pk >> 2;
            int t  = pk & 3;
            if (t < 3) {
                float v = __ldg(states + j * D + lane);
                if (t == 1) {
                    a1 += v; n1 += 1.f;
                    fm += __ldg(g_msg + j * D + lane);
                } else if (t == 0) { a0 += v; n0 += 1.f; }
                else               { a2 += v; n2 += 1.f; }
            }
        }
        a0 = __fdividef(a0, fmaxf(n0, 1.f));
        a1 = __fdividef(a1, fmaxf(n1, 1.f));
        a2 = __fdividef(a2, fmaxf(n2, 1.f));
        fm = __fdividef(fm, fmaxf(n1, 1.f));

        A1[c] = a1;
        inb[c * D + lane] = make_float4(cu, a0, fm, a2);   // STS.128
    }
    __syncwarp();

    // ---- fused pass: loc, fun, and CNF conditioning half (h2), 4 cells ----
    float accL[CPW], accF[CPW], h2[CPW];
    {
        const float bl = __ldg(b_loc + lane);
        const float bf = __ldg(b_fun + lane);
        const float bc = __ldg(b_cnf + lane);
#pragma unroll
        for (int c = 0; c < CPW; c++) { accL[c] = bl; accF[c] = bf; h2[c] = bc; }
    }

#pragma unroll
    for (int i = 0; i < D; i++) {
        const float wlT = sWloc[i * WSTR + lane];
        const float wlB = sWloc[(D + i) * WSTR + lane];
        const float wfT = sWfun[i * WSTR + lane];
        const float wfB = sWfun[(D + i) * WSTR + lane];
        const float wcB = sWcnf[(D + i) * WSTR + lane];
#pragma unroll
        for (int c = 0; c < CPW; c++) {
            const float4 xi = inb[c * D + i];       // broadcast LDS.128
            accL[c] = fmaf(xi.x, wlT, fmaf(xi.y, wlB, accL[c]));
            accF[c] = fmaf(xi.x, wfT, fmaf(xi.z, wfB, accF[c]));
            h2[c]   = fmaf(xi.w, wcB, h2[c]);
        }
    }
    float loc[CPW], fun[CPW], x[CPW];
#pragma unroll
    for (int c = 0; c < CPW; c++) {
        loc[c] = tanh_fast(accL[c]);
        fun[c] = tanh_fast(accF[c]);
        x[c]   = inb[c * D + lane].x;               // cur re-read (frees regs)
    }

    // ---- CNF: 3 explicit-Euler steps, top half only (h2 reused) ----
#pragma unroll
    for (int s = 0; s < 3; s++) {
        __syncwarp();
#pragma unroll
        for (int c = 0; c < CPW; c++) xxb[c * XSTR + lane] = x[c];
        __syncwarp();
        float acc[CPW];
#pragma unroll
        for (int c = 0; c < CPW; c++) acc[c] = h2[c];
#pragma unroll
        for (int i8 = 0; i8 < 8; i8++) {
            const float w0 = sWcnf[(4 * i8 + 0) * WSTR + lane];
            const float w1 = sWcnf[(4 * i8 + 1) * WSTR + lane];
            const float w2 = sWcnf[(4 * i8 + 2) * WSTR + lane];
            const float w3 = sWcnf[(4 * i8 + 3) * WSTR + lane];
#pragma unroll
            for (int c = 0; c < CPW; c++) {
                const float4 xv = *reinterpret_cast<const float4*>(xxb + c * XSTR + 4 * i8);
                acc[c] = fmaf(xv.x, w0, fmaf(xv.y, w1, fmaf(xv.z, w2, fmaf(xv.w, w3, acc[c]))));
            }
        }
#pragma unroll
        for (int c = 0; c < CPW; c++)
            x[c] = fmaf(1.0f / 3.0f, tanh_fast(acc[c]), x[c]);
    }

    // ---- gate: weights loaded HERE (short live range) + butterfly ----
    float wg[4][3];
#pragma unroll
    for (int s = 0; s < 4; s++)
#pragma unroll
        for (int e = 0; e < 3; e++)
            wg[s][e] = __ldg(W_gate + (s * D + lane) * 3 + e);
    const float bg0 = __ldg(b_gate + 0), bg1 = __ldg(b_gate + 1), bg2 = __ldg(b_gate + 2);

#pragma unroll
    for (int c = 0; c < CPW; c++) {
        const float4 gi = inb[c * D + lane];        // (cur, a0, fm, a2) per lane
        float p0 = gi.x * wg[0][0] + gi.y * wg[1][0] + A1[c] * wg[2][0] + gi.w * wg[3][0];
        float p1 = gi.x * wg[0][1] + gi.y * wg[1][1] + A1[c] * wg[2][1] + gi.w * wg[3][1];
        float p2 = gi.x * wg[0][2] + gi.y * wg[1][2] + A1[c] * wg[2][2] + gi.w * wg[3][2];
#pragma unroll
        for (int o = 16; o > 0; o >>= 1) {
            p0 += __shfl_xor_sync(FULL, p0, o);
            p1 += __shfl_xor_sync(FULL, p1, o);
            p2 += __shfl_xor_sync(FULL, p2, o);
        }
        const float g0 = p0 + bg0, g1 = p1 + bg1, g2 = p2 + bg2;
        const float mx = fmaxf(g0, fmaxf(g1, g2));
        const float e0 = __expf(g0 - mx), e1 = __expf(g1 - mx), e2 = __expf(g2 - mx);
        const float inv = __fdividef(1.f, e0 + e1 + e2);

        const int cell = base + c;
        if (cell < n)
            out[cell * D + lane] = (e0 * loc[c] + e1 * fun[c] + e2 * x[c]) * inv;
    }
}

extern "C" void kernel_launch(void* const* d_in, const int* in_sizes, int n_in,
                              void* d_out, int out_size) {
    const float* states = (const float*)d_in[0];
    const int*   nbr    = (const int*)  d_in[1];
    const int*   tiers  = (const int*)  d_in[2];
    const float* W_loc  = (const float*)d_in[3];
    const float* b_loc  = (const float*)d_in[4];
    const float* W_msg  = (const float*)d_in[5];
    const float* b_msg  = (const float*)d_in[6];
    const float* W_fun  = (const float*)d_in[7];
    const float* b_fun  = (const float*)d_in[8];
    const float* W_cnf  = (const float*)d_in[9];
    const float* b_cnf  = (const float*)d_in[10];
    const float* W_gate = (const float*)d_in[11];
    const float* b_gate = (const float*)d_in[12];
    float* out = (float*)d_out;

    const int n = in_sizes[0] / D;
    const int blocks = (n + WPB * CPW - 1) / (WPB * CPW);

    msg_prepass<<<blocks, TPB>>>(n, states, W_msg, b_msg);
    moe_main<<<blocks, TPB>>>(n, states, nbr, tiers,
                              W_loc, b_loc, W_fun, b_fun,
                              W_cnf, b_cnf, W_gate, b_gate, out);
}

// round 4
// speedup vs baseline: 2.3284x; 1.1618x over previous
#include <cuda_runtime.h>

#define D    32
#define KN   26
#define CPW  4              // cells per warp
#define WPB  8              // warps per block
#define TPB  (WPB * 32)
#define NMAX 125000
#define XSTR 36             // x staging row stride (16B-aligned float4 reads)

__device__ float g_msg[NMAX * D];   // precomputed tanh(state @ W_msg + b_msg)

__device__ __forceinline__ float tanh_fast(float x) {
    float y;
    asm("tanh.approx.f32 %0, %1;" : "=f"(y) : "f"(x));
    return y;
}

// ---------------------------------------------------------------------------
// Prepass: g_msg[cell] = tanh(states[cell] @ W_msg + b_msg)   (per SOURCE cell)
// ---------------------------------------------------------------------------
__global__ __launch_bounds__(TPB) void msg_prepass(
    int n, const float* __restrict__ states,
    const float* __restrict__ W_msg, const float* __restrict__ b_msg)
{
    __shared__ float sx[WPB][CPW * XSTR];
    const int lane = threadIdx.x & 31, warp = threadIdx.x >> 5;
    const int base = (blockIdx.x * WPB + warp) * CPW;
    if (base >= n) return;

    float wm[D];                                   // lane holds W_msg[:, lane]
#pragma unroll
    for (int i = 0; i < D; i++) wm[i] = __ldg(W_msg + i * D + lane);
    const float bm = __ldg(b_msg + lane);

    float* xb = sx[warp];
#pragma unroll
    for (int c = 0; c < CPW; c++) {
        int cell = base + c;
        xb[c * XSTR + lane] = (cell < n) ? states[cell * D + lane] : 0.f;
    }
    __syncwarp();
#pragma unroll
    for (int c = 0; c < CPW; c++) {
        int cell = base + c;
        float m = bm;
#pragma unroll
        for (int i8 = 0; i8 < 8; i8++) {
            float4 xv = *reinterpret_cast<const float4*>(xb + c * XSTR + 4 * i8);
            m = fmaf(xv.x, wm[4 * i8 + 0], m);
            m = fmaf(xv.y, wm[4 * i8 + 1], m);
            m = fmaf(xv.z, wm[4 * i8 + 2], m);
            m = fmaf(xv.w, wm[4 * i8 + 3], m);
        }
        if (cell < n) g_msg[cell * D + lane] = tanh_fast(m);
    }
}

// ---------------------------------------------------------------------------
// Main kernel: branchless gather, float4 weights, 4 cells/warp
// ---------------------------------------------------------------------------
__global__ __launch_bounds__(TPB, 5) void moe_main(
    int n,
    const float* __restrict__ states,
    const int*   __restrict__ nbr,
    const int*   __restrict__ tiers,
    const float* __restrict__ W_loc,  const float* __restrict__ b_loc,
    const float* __restrict__ W_fun,  const float* __restrict__ b_fun,
    const float* __restrict__ W_cnf,  const float* __restrict__ b_cnf,
    const float* __restrict__ W_gate, const float* __restrict__ b_gate,
    float* __restrict__ out)
{
    __shared__ float4 sWloc4[16 * 32];   // [i4*32 + lane] = {W[4i4..4i4+3][lane]}
    __shared__ float4 sWfun4[16 * 32];
    __shared__ float4 sWcnf4[16 * 32];
    __shared__ float4 sIn[WPB][CPW * D]; // {cur, a0, fmsg, a2} per (cell, i)
    __shared__ float  sX[WPB][CPW * XSTR];

    // stage weights packed over i (4 coalesced LDG.32 -> 1 STS.128)
    for (int e = threadIdx.x; e < 16 * 32; e += TPB) {
        int i = (e >> 5) * 4, j = e & 31;
        sWloc4[e] = make_float4(W_loc[i * 32 + j], W_loc[(i + 1) * 32 + j],
                                W_loc[(i + 2) * 32 + j], W_loc[(i + 3) * 32 + j]);
        sWfun4[e] = make_float4(W_fun[i * 32 + j], W_fun[(i + 1) * 32 + j],
                                W_fun[(i + 2) * 32 + j], W_fun[(i + 3) * 32 + j]);
        sWcnf4[e] = make_float4(W_cnf[i * 32 + j], W_cnf[(i + 1) * 32 + j],
                                W_cnf[(i + 2) * 32 + j], W_cnf[(i + 3) * 32 + j]);
    }
    __syncthreads();

    const int lane = threadIdx.x & 31, warp = threadIdx.x >> 5;
    const int base = (blockIdx.x * WPB + warp) * CPW;
    if (base >= n) return;
    const unsigned FULL = 0xffffffffu;

    const char* sb = (const char*)states + lane * 4;   // lane-offset byte bases
    const char* mb = (const char*)g_msg  + lane * 4;

    float4* inb = sIn[warp];
    float*  xxb = sX[warp];
    float   A1[CPW];

    // ---- gather + tier means + message gather (branchless) ----
#pragma unroll
    for (int c = 0; c < CPW; c++) {
        const int cell = base + c;
        const bool act = (cell < n);

        float cu = act ? states[cell * D + lane] : 0.f;
        int mypk = 3;                                  // tier 3 = inactive
        int myt  = 3;
        if (act && lane < KN) {
            int idx = __ldg(nbr   + cell * KN + lane);
            myt     = __ldg(tiers + cell * KN + lane);
            mypk    = idx * 128 + myt;                 // byte offset | tier
        }
        const unsigned mask0 = __ballot_sync(FULL, myt == 0);
        const unsigned mask1 = __ballot_sync(FULL, myt == 1);
        const float n0 = (float)__popc(mask0);
        const float n1 = (float)__popc(mask1);
        const float n2 = act ? (float)(KN) - n0 - n1 : 0.f;

        float a0 = 0.f, a1 = 0.f, tot = 0.f;
#pragma unroll
        for (int k = 0; k < KN; k++) {
            const int pk  = __shfl_sync(FULL, mypk, k);          // warp-uniform
            const int t   = pk & 3;
            const float v = __ldg((const float*)(sb + (pk & ~127)));
            tot += v;
            a0  += (t == 0) ? v : 0.f;                           // predicated
            a1  += (t == 1) ? v : 0.f;
        }
        float a2 = tot - a0 - a1;

        float fm = 0.f;
        unsigned m = mask1;                                      // warp-uniform loop
        while (m) {
            const int k = __ffs(m) - 1;
            m &= m - 1;
            const int pk = __shfl_sync(FULL, mypk, k);
            fm += __ldg((const float*)(mb + (pk & ~127)));
        }

        a0 = __fdividef(a0, fmaxf(n0, 1.f));
        a1 = __fdividef(a1, fmaxf(n1, 1.f));
        a2 = __fdividef(a2, fmaxf(n2, 1.f));
        fm = __fdividef(fm, fmaxf(n1, 1.f));

        A1[c] = a1;
        inb[c * D + lane] = make_float4(cu, a0, fm, a2);         // STS.128
    }
    __syncwarp();

    // ---- fused pass: loc, fun, CNF conditioning half (h2); packed weights ----
    float accL[CPW], accF[CPW], h2[CPW];
    {
        const float bl = __ldg(b_loc + lane);
        const float bf = __ldg(b_fun + lane);
        const float bc = __ldg(b_cnf + lane);
#pragma unroll
        for (int c = 0; c < CPW; c++) { accL[c] = bl; accF[c] = bf; h2[c] = bc; }
    }

#pragma unroll
    for (int i4 = 0; i4 < 8; i4++) {
        const float4 wlT = sWloc4[i4 * 32 + lane];        // rows 4i4..4i4+3 (top)
        const float4 wlB = sWloc4[(i4 + 8) * 32 + lane];  // rows 32+...
        const float4 wfT = sWfun4[i4 * 32 + lane];
        const float4 wfB = sWfun4[(i4 + 8) * 32 + lane];
        const float4 wcB = sWcnf4[(i4 + 8) * 32 + lane];
#pragma unroll
        for (int c = 0; c < CPW; c++) {
            const float4 x0 = inb[c * D + 4 * i4 + 0];    // broadcast LDS.128
            const float4 x1 = inb[c * D + 4 * i4 + 1];
            const float4 x2 = inb[c * D + 4 * i4 + 2];
            const float4 x3 = inb[c * D + 4 * i4 + 3];
            accL[c] = fmaf(x0.x, wlT.x, fmaf(x0.y, wlB.x, accL[c]));
            accL[c] = fmaf(x1.x, wlT.y, fmaf(x1.y, wlB.y, accL[c]));
            accL[c] = fmaf(x2.x, wlT.z, fmaf(x2.y, wlB.z, accL[c]));
            accL[c] = fmaf(x3.x, wlT.w, fmaf(x3.y, wlB.w, accL[c]));
            accF[c] = fmaf(x0.x, wfT.x, fmaf(x0.z, wfB.x, accF[c]));
            accF[c] = fmaf(x1.x, wfT.y, fmaf(x1.z, wfB.y, accF[c]));
            accF[c] = fmaf(x2.x, wfT.z, fmaf(x2.z, wfB.z, accF[c]));
            accF[c] = fmaf(x3.x, wfT.w, fmaf(x3.z, wfB.w, accF[c]));
            h2[c]   = fmaf(x0.w, wcB.x, h2[c]);
            h2[c]   = fmaf(x1.w, wcB.y, h2[c]);
            h2[c]   = fmaf(x2.w, wcB.z, h2[c]);
            h2[c]   = fmaf(x3.w, wcB.w, h2[c]);
        }
    }
    float loc[CPW], fun[CPW], x[CPW];
#pragma unroll
    for (int c = 0; c < CPW; c++) {
        loc[c] = tanh_fast(accL[c]);
        fun[c] = tanh_fast(accF[c]);
        x[c]   = inb[c * D + lane].x;               // cur re-read
    }

    // ---- CNF: 3 explicit-Euler steps, top half only (h2 reused) ----
#pragma unroll
    for (int s = 0; s < 3; s++) {
        __syncwarp();
#pragma unroll
        for (int c = 0; c < CPW; c++) xxb[c * XSTR + lane] = x[c];
        __syncwarp();
        float acc[CPW];
#pragma unroll
        for (int c = 0; c < CPW; c++) acc[c] = h2[c];
#pragma unroll
        for (int i4 = 0; i4 < 8; i4++) {
            const float4 w = sWcnf4[i4 * 32 + lane];              // top rows
#pragma unroll
            for (int c = 0; c < CPW; c++) {
                const float4 xv = *reinterpret_cast<const float4*>(xxb + c * XSTR + 4 * i4);
                acc[c] = fmaf(xv.x, w.x, fmaf(xv.y, w.y, fmaf(xv.z, w.z, fmaf(xv.w, w.w, acc[c]))));
            }
        }
#pragma unroll
        for (int c = 0; c < CPW; c++)
            x[c] = fmaf(1.0f / 3.0f, tanh_fast(acc[c]), x[c]);
    }

    // ---- gate: weights loaded here (short live range) + butterfly ----
    float wg[4][3];
#pragma unroll
    for (int s = 0; s < 4; s++)
#pragma unroll
        for (int e = 0; e < 3; e++)
            wg[s][e] = __ldg(W_gate + (s * D + lane) * 3 + e);
    const float bg0 = __ldg(b_gate + 0), bg1 = __ldg(b_gate + 1), bg2 = __ldg(b_gate + 2);

#pragma unroll
    for (int c = 0; c < CPW; c++) {
        const float4 gi = inb[c * D + lane];        // (cur, a0, fm, a2) per lane
        float p0 = gi.x * wg[0][0] + gi.y * wg[1][0] + A1[c] * wg[2][0] + gi.w * wg[3][0];
        float p1 = gi.x * wg[0][1] + gi.y * wg[1][1] + A1[c] * wg[2][1] + gi.w * wg[3][1];
        float p2 = gi.x * wg[0][2] + gi.y * wg[1][2] + A1[c] * wg[2][2] + gi.w * wg[3][2];
#pragma unroll
        for (int o = 16; o > 0; o >>= 1) {
            p0 += __shfl_xor_sync(FULL, p0, o);
            p1 += __shfl_xor_sync(FULL, p1, o);
            p2 += __shfl_xor_sync(FULL, p2, o);
        }
        const float g0 = p0 + bg0, g1 = p1 + bg1, g2 = p2 + bg2;
        const float mx = fmaxf(g0, fmaxf(g1, g2));
        const float e0 = __expf(g0 - mx), e1 = __expf(g1 - mx), e2 = __expf(g2 - mx);
        const float inv = __fdividef(1.f, e0 + e1 + e2);

        const int cell = base + c;
        if (cell < n)
            out[cell * D + lane] = (e0 * loc[c] + e1 * fun[c] + e2 * x[c]) * inv;
    }
}

extern "C" void kernel_launch(void* const* d_in, const int* in_sizes, int n_in,
                              void* d_out, int out_size) {
    const float* states = (const float*)d_in[0];
    const int*   nbr    = (const int*)  d_in[1];
    const int*   tiers  = (const int*)  d_in[2];
    const float* W_loc  = (const float*)d_in[3];
    const float* b_loc  = (const float*)d_in[4];
    const float* W_msg  = (const float*)d_in[5];
    const float* b_msg  = (const float*)d_in[6];
    const float* W_fun  = (const float*)d_in[7];
    const float* b_fun  = (const float*)d_in[8];
    const float* W_cnf  = (const float*)d_in[9];
    const float* b_cnf  = (const float*)d_in[10];
    const float* W_gate = (const float*)d_in[11];
    const float* b_gate = (const float*)d_in[12];
    float* out = (float*)d_out;

    const int n = in_sizes[0] / D;
    const int blocks = (n + WPB * CPW - 1) / (WPB * CPW);

    msg_prepass<<<blocks, TPB>>>(n, states, W_msg, b_msg);
    moe_main<<<blocks, TPB>>>(n, states, nbr, tiers,
                              W_loc, b_loc, W_fun, b_fun,
                              W_cnf, b_cnf, W_gate, b_gate, out);
}

// round 5
// speedup vs baseline: 2.4871x; 1.0682x over previous
#include <cuda_runtime.h>

#define D    32
#define KN   26
#define CPW  4               // cells per warp
#define WPB  12              // warps per block
#define TPB  (WPB * 32)
#define NMAX 125000
#define XSTR 36              // x staging row stride (16B-aligned float4 reads)

__device__ float g_msg[NMAX * D];   // precomputed tanh(state @ W_msg + b_msg)

__device__ __forceinline__ float tanh_fast(float x) {
    float y;
    asm("tanh.approx.f32 %0, %1;" : "=f"(y) : "f"(x));
    return y;
}

// ---------------------------------------------------------------------------
// Prepass: g_msg[cell] = tanh(states[cell] @ W_msg + b_msg)   (per SOURCE cell)
// ---------------------------------------------------------------------------
__global__ __launch_bounds__(TPB) void msg_prepass(
    int n, const float* __restrict__ states,
    const float* __restrict__ W_msg, const float* __restrict__ b_msg)
{
    __shared__ float sx[WPB][CPW * XSTR];
    const int lane = threadIdx.x & 31, warp = threadIdx.x >> 5;
    const int base = (blockIdx.x * WPB + warp) * CPW;
    if (base >= n) return;

    float wm[D];                                   // lane holds W_msg[:, lane]
#pragma unroll
    for (int i = 0; i < D; i++) wm[i] = __ldg(W_msg + i * D + lane);
    const float bm = __ldg(b_msg + lane);

    float* xb = sx[warp];
#pragma unroll
    for (int c = 0; c < CPW; c++) {
        int cell = base + c;
        xb[c * XSTR + lane] = (cell < n) ? states[cell * D + lane] : 0.f;
    }
    __syncwarp();
#pragma unroll
    for (int c = 0; c < CPW; c++) {
        int cell = base + c;
        float m = bm;
#pragma unroll
        for (int i8 = 0; i8 < 8; i8++) {
            float4 xv = *reinterpret_cast<const float4*>(xb + c * XSTR + 4 * i8);
            m = fmaf(xv.x, wm[4 * i8 + 0], m);
            m = fmaf(xv.y, wm[4 * i8 + 1], m);
            m = fmaf(xv.z, wm[4 * i8 + 2], m);
            m = fmaf(xv.w, wm[4 * i8 + 3], m);
        }
        if (cell < n) g_msg[cell * D + lane] = tanh_fast(m);
    }
}

// ---------------------------------------------------------------------------
// Main kernel: 48 warps/SM, branchless gather w/ predicated msg LDG
// ---------------------------------------------------------------------------
__global__ __launch_bounds__(TPB, 4) void moe_main(
    int n,
    const float* __restrict__ states,
    const int*   __restrict__ nbr,
    const int*   __restrict__ tiers,
    const float* __restrict__ W_loc,  const float* __restrict__ b_loc,
    const float* __restrict__ W_fun,  const float* __restrict__ b_fun,
    const float* __restrict__ W_cnf,  const float* __restrict__ b_cnf,
    const float* __restrict__ W_gate, const float* __restrict__ b_gate,
    float* __restrict__ out)
{
    extern __shared__ char smem[];
    float4* sWloc4 = reinterpret_cast<float4*>(smem);                 // 16*32 float4
    float4* sWfun4 = sWloc4 + 16 * 32;
    float4* sWcnf4 = sWfun4 + 16 * 32;
    float4* sInAll = sWcnf4 + 16 * 32;                                // WPB*CPW*32 float4
    float*  sXAll  = reinterpret_cast<float*>(sInAll + WPB * CPW * D); // WPB*CPW*XSTR

    // stage weights packed over i (4 coalesced LDG.32 -> 1 STS.128)
    for (int e = threadIdx.x; e < 16 * 32; e += TPB) {
        int i = (e >> 5) * 4, j = e & 31;
        sWloc4[e] = make_float4(W_loc[i * 32 + j], W_loc[(i + 1) * 32 + j],
                                W_loc[(i + 2) * 32 + j], W_loc[(i + 3) * 32 + j]);
        sWfun4[e] = make_float4(W_fun[i * 32 + j], W_fun[(i + 1) * 32 + j],
                                W_fun[(i + 2) * 32 + j], W_fun[(i + 3) * 32 + j]);
        sWcnf4[e] = make_float4(W_cnf[i * 32 + j], W_cnf[(i + 1) * 32 + j],
                                W_cnf[(i + 2) * 32 + j], W_cnf[(i + 3) * 32 + j]);
    }
    __syncthreads();

    const int lane = threadIdx.x & 31, warp = threadIdx.x >> 5;
    const int base = (blockIdx.x * WPB + warp) * CPW;
    if (base >= n) return;
    const unsigned FULL = 0xffffffffu;

    const char* sb = (const char*)states + lane * 4;   // lane-offset byte bases
    const char* mb = (const char*)g_msg  + lane * 4;

    float4* inb = sInAll + warp * (CPW * D);
    float*  xxb = sXAll  + warp * (CPW * XSTR);
    float   A1[CPW];

    // ---- gather + tier means + message gather (branchless) ----
#pragma unroll
    for (int c = 0; c < CPW; c++) {
        const int cell = base + c;
        const bool act = (cell < n);

        float cu = act ? states[cell * D + lane] : 0.f;
        int mypk = 3;                                  // tier 3 = inactive
        int myt  = 3;
        if (act && lane < KN) {
            int idx = __ldg(nbr   + cell * KN + lane);
            myt     = __ldg(tiers + cell * KN + lane);
            mypk    = idx * 128 + myt;                 // byte offset | tier
        }
        const unsigned mask0 = __ballot_sync(FULL, myt == 0);
        const unsigned mask1 = __ballot_sync(FULL, myt == 1);
        const float n0 = (float)__popc(mask0);
        const float n1 = (float)__popc(mask1);
        const float n2 = act ? (float)(KN) - n0 - n1 : 0.f;

        float a0 = 0.f, a1 = 0.f, tot = 0.f, fm = 0.f;
#pragma unroll
        for (int k = 0; k < KN; k++) {
            const int pk  = __shfl_sync(FULL, mypk, k);           // warp-uniform
            const int t   = pk & 3;
            const long off = (long)(pk & ~127);
            const float v = __ldg((const float*)(sb + off));
            // guaranteed-predicated msg load: only tier-1 neighbors touch g_msg
            float mv;
            asm("{ .reg .pred p;\n\t"
                "  setp.eq.s32 p, %1, 1;\n\t"
                "  mov.f32 %0, 0f00000000;\n\t"
                "  @p ld.global.nc.f32 %0, [%2];\n\t"
                "}" : "=f"(mv) : "r"(t), "l"(mb + off));
            tot += v;
            a0  += (t == 0) ? v : 0.f;                            // predicated
            a1  += (t == 1) ? v : 0.f;
            fm  += mv;
        }
        float a2 = tot - a0 - a1;

        a0 = __fdividef(a0, fmaxf(n0, 1.f));
        a1 = __fdividef(a1, fmaxf(n1, 1.f));
        a2 = __fdividef(a2, fmaxf(n2, 1.f));
        fm = __fdividef(fm, fmaxf(n1, 1.f));

        A1[c] = a1;
        inb[c * D + lane] = make_float4(cu, a0, fm, a2);          // STS.128
    }
    __syncwarp();

    // ---- fused pass: loc, fun, CNF conditioning half (h2); packed weights ----
    float accL[CPW], accF[CPW], h2[CPW];
    {
        const float bl = __ldg(b_loc + lane);
        const float bf = __ldg(b_fun + lane);
        const float bc = __ldg(b_cnf + lane);
#pragma unroll
        for (int c = 0; c < CPW; c++) { accL[c] = bl; accF[c] = bf; h2[c] = bc; }
    }

#pragma unroll
    for (int i4 = 0; i4 < 8; i4++) {
        const float4 wlT = sWloc4[i4 * 32 + lane];        // rows 4i4..4i4+3 (top)
        const float4 wlB = sWloc4[(i4 + 8) * 32 + lane];  // rows 32+...
        const float4 wfT = sWfun4[i4 * 32 + lane];
        const float4 wfB = sWfun4[(i4 + 8) * 32 + lane];
        const float4 wcB = sWcnf4[(i4 + 8) * 32 + lane];
#pragma unroll
        for (int c = 0; c < CPW; c++) {
            const float4 x0 = inb[c * D + 4 * i4 + 0];    // broadcast LDS.128
            const float4 x1 = inb[c * D + 4 * i4 + 1];
            const float4 x2 = inb[c * D + 4 * i4 + 2];
            const float4 x3 = inb[c * D + 4 * i4 + 3];
            accL[c] = fmaf(x0.x, wlT.x, fmaf(x0.y, wlB.x, accL[c]));
            accL[c] = fmaf(x1.x, wlT.y, fmaf(x1.y, wlB.y, accL[c]));
            accL[c] = fmaf(x2.x, wlT.z, fmaf(x2.y, wlB.z, accL[c]));
            accL[c] = fmaf(x3.x, wlT.w, fmaf(x3.y, wlB.w, accL[c]));
            accF[c] = fmaf(x0.x, wfT.x, fmaf(x0.z, wfB.x, accF[c]));
            accF[c] = fmaf(x1.x, wfT.y, fmaf(x1.z, wfB.y, accF[c]));
            accF[c] = fmaf(x2.x, wfT.z, fmaf(x2.z, wfB.z, accF[c]));
            accF[c] = fmaf(x3.x, wfT.w, fmaf(x3.z, wfB.w, accF[c]));
            h2[c]   = fmaf(x0.w, wcB.x, h2[c]);
            h2[c]   = fmaf(x1.w, wcB.y, h2[c]);
            h2[c]   = fmaf(x2.w, wcB.z, h2[c]);
            h2[c]   = fmaf(x3.w, wcB.w, h2[c]);
        }
    }
    float loc[CPW], fun[CPW], x[CPW];
#pragma unroll
    for (int c = 0; c < CPW; c++) {
        loc[c] = tanh_fast(accL[c]);
        fun[c] = tanh_fast(accF[c]);
        x[c]   = inb[c * D + lane].x;               // cur re-read
    }

    // ---- CNF: 3 explicit-Euler steps, top half only (h2 reused) ----
#pragma unroll
    for (int s = 0; s < 3; s++) {
        __syncwarp();
#pragma unroll
        for (int c = 0; c < CPW; c++) xxb[c * XSTR + lane] = x[c];
        __syncwarp();
        float acc[CPW];
#pragma unroll
        for (int c = 0; c < CPW; c++) acc[c] = h2[c];
#pragma unroll
        for (int i4 = 0; i4 < 8; i4++) {
            const float4 w = sWcnf4[i4 * 32 + lane];              // top rows
#pragma unroll
            for (int c = 0; c < CPW; c++) {
                const float4 xv = *reinterpret_cast<const float4*>(xxb + c * XSTR + 4 * i4);
                acc[c] = fmaf(xv.x, w.x, fmaf(xv.y, w.y, fmaf(xv.z, w.z, fmaf(xv.w, w.w, acc[c]))));
            }
        }
#pragma unroll
        for (int c = 0; c < CPW; c++)
            x[c] = fmaf(1.0f / 3.0f, tanh_fast(acc[c]), x[c]);
    }

    // ---- gate: weights loaded here (short live range) + butterfly ----
    float wg[4][3];
#pragma unroll
    for (int s = 0; s < 4; s++)
#pragma unroll
        for (int e = 0; e < 3; e++)
            wg[s][e] = __ldg(W_gate + (s * D + lane) * 3 + e);
    const float bg0 = __ldg(b_gate + 0), bg1 = __ldg(b_gate + 1), bg2 = __ldg(b_gate + 2);

#pragma unroll
    for (int c = 0; c < CPW; c++) {
        const float4 gi = inb[c * D + lane];        // (cur, a0, fm, a2) per lane
        float p0 = gi.x * wg[0][0] + gi.y * wg[1][0] + A1[c] * wg[2][0] + gi.w * wg[3][0];
        float p1 = gi.x * wg[0][1] + gi.y * wg[1][1] + A1[c] * wg[2][1] + gi.w * wg[3][1];
        float p2 = gi.x * wg[0][2] + gi.y * wg[1][2] + A1[c] * wg[2][2] + gi.w * wg[3][2];
#pragma unroll
        for (int o = 16; o > 0; o >>= 1) {
            p0 += __shfl_xor_sync(FULL, p0, o);
            p1 += __shfl_xor_sync(FULL, p1, o);
            p2 += __shfl_xor_sync(FULL, p2, o);
        }
        const float g0 = p0 + bg0, g1 = p1 + bg1, g2 = p2 + bg2;
        const float mx = fmaxf(g0, fmaxf(g1, g2));
        const float e0 = __expf(g0 - mx), e1 = __expf(g1 - mx), e2 = __expf(g2 - mx);
        const float inv = __fdividef(1.f, e0 + e1 + e2);

        const int cell = base + c;
        if (cell < n)
            out[cell * D + lane] = (e0 * loc[c] + e1 * fun[c] + e2 * x[c]) * inv;
    }
}

extern "C" void kernel_launch(void* const* d_in, const int* in_sizes, int n_in,
                              void* d_out, int out_size) {
    const float* states = (const float*)d_in[0];
    const int*   nbr    = (const int*)  d_in[1];
    const int*   tiers  = (const int*)  d_in[2];
    const float* W_loc  = (const float*)d_in[3];
    const float* b_loc  = (const float*)d_in[4];
    const float* W_msg  = (const float*)d_in[5];
    const float* b_msg  = (const float*)d_in[6];
    const float* W_fun  = (const float*)d_in[7];
    const float* b_fun  = (const float*)d_in[8];
    const float* W_cnf  = (const float*)d_in[9];
    const float* b_cnf  = (const float*)d_in[10];
    const float* W_gate = (const float*)d_in[11];
    const float* b_gate = (const float*)d_in[12];
    float* out = (float*)d_out;

    const int n = in_sizes[0] / D;
    const int blocks = (n + WPB * CPW - 1) / (WPB * CPW);

    // dynamic smem: 3 weight arrays + input staging + CNF x staging
    const int smem_bytes = (3 * 16 * 32) * (int)sizeof(float4)
                         + (WPB * CPW * D) * (int)sizeof(float4)
                         + (WPB * CPW * XSTR) * (int)sizeof(float);
    static bool attr_set = false;
    if (!attr_set) {
        cudaFuncSetAttribute(moe_main, cudaFuncAttributeMaxDynamicSharedMemorySize, smem_bytes);
        attr_set = true;
    }

    msg_prepass<<<blocks, TPB>>>(n, states, W_msg, b_msg);
    moe_main<<<blocks, TPB, smem_bytes>>>(n, states, nbr, tiers,
                                          W_loc, b_loc, W_fun, b_fun,
                                          W_cnf, b_cnf, W_gate, b_gate, out);
}